// round 17
// baseline (speedup 1.0000x reference)
#include <cuda_runtime.h>
#include <cuda_bf16.h>
#include <cuda_fp16.h>
#include <mma.h>
#include <cstdint>

using namespace nvcuda;

#define NMAX 20000
#define XPAD 20096           // NMAX rounded up to 128-row tiles
#define EMAX 320000
#define D 256
#define NC 512   // self 256 cols | neigh 256 cols

// ---------------- scratch (__device__ globals) ----------------------------------
__device__ __align__(16) __nv_bfloat16 g_Xhi[(size_t)XPAD * D];
__device__ __align__(16) __nv_bfloat16 g_Xlo[(size_t)XPAD * D];
__device__ __align__(16) __nv_bfloat16 g_Whi[NC * D];   // [n][k], K-major
__device__ __align__(16) __nv_bfloat16 g_Wlo[NC * D];
__device__ __align__(16) float g_Cs[(size_t)XPAD * D];  // normalized self half, f32
__device__ __align__(16) __half g_Nh[(size_t)XPAD * D]; // normalized neigh half, fp16
__device__ float g_habs[NMAX];
__device__ int g_deg[NMAX];     // zero-initialized at load; agg re-zeroes each call
__device__ int g_off[NMAX + 1];
__device__ int g_cur[NMAX];
__device__ int g_bucket[EMAX];
__device__ int g_bsum[160];
__device__ int g_bpre[160];

__device__ __forceinline__ float warp_sum(float v) {
#pragma unroll
    for (int o = 16; o > 0; o >>= 1) v += __shfl_xor_sync(0xffffffffu, v, o);
    return v;
}
__device__ __forceinline__ uint32_t smem_u32(const void* p) {
    uint32_t a;
    asm("{ .reg .u64 t; cvta.to.shared.u64 t, %1; cvt.u32.u64 %0, t; }" : "=r"(a) : "l"(p));
    return a;
}
#define CP_ASYNC16(dst, src) \
    asm volatile("cp.async.cg.shared.global [%0], [%1], 16;" :: "r"(dst), "l"(src))
#define CP_COMMIT() asm volatile("cp.async.commit_group;" ::: "memory")
#define CP_WAIT(n)  asm volatile("cp.async.wait_group %0;" :: "n"(n) : "memory")

// ---------------- 1. fused: per-node normalize+split  |  W concat+split ---------
__global__ void prep_wsplit_kernel(const float* __restrict__ x,
                                   const float* __restrict__ Ws,
                                   const float* __restrict__ Wn,
                                   int N, int PB) {
    if (blockIdx.x < PB) {
        int gid = blockIdx.x * blockDim.x + threadIdx.x;
        int w = gid >> 5;
        int lane = threadIdx.x & 31;
        if (w >= N) return;
        const float* xr = x + (size_t)w * (D + 1);
        float v[8];
        float ss = 0.f;
        bool nz = false;
#pragma unroll
        for (int k = 0; k < 8; k++) {
            float t = xr[k * 32 + lane];
            v[k] = t; ss += t * t; nz |= (t != 0.f);
        }
        unsigned m = __ballot_sync(0xffffffffu, nz);
        ss = warp_sum(ss);
        float h = xr[D];
        float s0 = (h < 0.f) ? -1.f : 1.f;
        float scale;
        if (m == 0u) {
#pragma unroll
            for (int k = 0; k < 8; k++) v[k] = 1.f;
            scale = s0 * (1.f / 16.f);
        } else {
            scale = s0 / fmaxf(sqrtf(ss), 1e-8f);
        }
#pragma unroll
        for (int k = 0; k < 8; k++) {
            float val = v[k] * scale;
            __nv_bfloat16 hi = __float2bfloat16_rn(val);
            float lo = val - __bfloat162float(hi);
            size_t idx = (size_t)w * D + k * 32 + lane;
            g_Xhi[idx] = hi;
            g_Xlo[idx] = __float2bfloat16_rn(lo);
        }
        if (lane == 0) g_habs[w] = h * s0;
    } else {
        int idx = (blockIdx.x - PB) * blockDim.x + threadIdx.x;
        if (idx >= NC * D) return;
        int j = idx / D, k = idx % D;
        float w = (j < D) ? Ws[j * D + k] : Wn[(j - D) * D + k];
        __nv_bfloat16 hi = __float2bfloat16_rn(w);
        g_Whi[idx] = hi;
        g_Wlo[idx] = __float2bfloat16_rn(w - __bfloat162float(hi));
    }
}

// ---------------- 2. count edges per destination (g_deg zeroed by prior agg) ----
__global__ void count_kernel(const int* __restrict__ ei, int E) {
    int e = blockIdx.x * blockDim.x + threadIdx.x;
    if (e < E) atomicAdd(&g_deg[ei[e]], 1);
}

// ---------------- 3a/b/c. parallel exclusive scan -------------------------------
__global__ void scan1_kernel(int N) {
    __shared__ int sh[256];
    int t = threadIdx.x;
    int i = blockIdx.x * 256 + t;
    sh[t] = (i < N) ? g_deg[i] : 0;
    __syncthreads();
#pragma unroll
    for (int o = 128; o > 0; o >>= 1) {
        if (t < o) sh[t] += sh[t + o];
        __syncthreads();
    }
    if (t == 0) g_bsum[blockIdx.x] = sh[0];
}
__global__ void scan2_kernel(int NB, int N) {
    __shared__ int sh[160];
    int t = threadIdx.x;
    int v = (t < NB) ? g_bsum[t] : 0;
    sh[t] = v;
    __syncthreads();
    for (int o = 1; o < 160; o <<= 1) {
        int u = (t >= o) ? sh[t - o] : 0;
        __syncthreads();
        sh[t] += u;
        __syncthreads();
    }
    if (t < NB) g_bpre[t] = sh[t] - v;
    if (t == NB - 1) g_off[N] = sh[t];
}
__global__ void scan3_kernel(int N) {
    __shared__ int sh[256];
    int t = threadIdx.x;
    int i = blockIdx.x * 256 + t;
    int v = (i < N) ? g_deg[i] : 0;
    sh[t] = v;
    __syncthreads();
#pragma unroll
    for (int o = 1; o < 256; o <<= 1) {
        int u = (t >= o) ? sh[t - o] : 0;
        __syncthreads();
        sh[t] += u;
        __syncthreads();
    }
    if (i < N) {
        int e = sh[t] - v + g_bpre[blockIdx.x];
        g_off[i] = e;
        g_cur[i] = e;
    }
}

// ---------------- 4. bucket edge sources by destination -------------------------
__global__ void fill_kernel(const int* __restrict__ ei, int E) {
    int e = blockIdx.x * blockDim.x + threadIdx.x;
    if (e < E) {
        int r = ei[e];
        int c = ei[E + e];
        int p = atomicAdd(&g_cur[r], 1);
        g_bucket[p] = c;
    }
}

// ---------------- 5. WMMA bf16 3-term GEMM 128x256, fused row-normalize ---------
// CTA tile 128x256 covers a FULL output half-row -> normalization fused into
// epilogue. 8 warps, warp tile 64x64. 2-stage cp.async, K chunks of 32.
#define GLDM 40
#define A_ARR (128 * GLDM * 2)            // 10240 B
#define B_ARR (256 * GLDM * 2)            // 20480 B
#define STAGE_BYTES (2 * A_ARR + 2 * B_ARR)  // 61440
#define GEMM_SMEM 131072                  // epilogue buffer 128*256*4 dominates

__device__ __forceinline__ void gemm_stage_load(char* smem, int s, int row0, int j0,
                                                int kc, int tid) {
    char* base = smem + s * STAGE_BYTES;
    uint32_t uAhi = smem_u32(base);
    uint32_t uAlo = uAhi + A_ARR;
    uint32_t uBhi = uAlo + A_ARR;
    uint32_t uBlo = uBhi + B_ARR;
#pragma unroll
    for (int t = 0; t < 2; t++) {
        int o = tid + t * 256;            // 0..511
        int row = o >> 2, seg = o & 3;
        uint32_t doff = row * 80 + seg * 16;
        size_t aoff = (size_t)(row0 + row) * D + kc + seg * 8;
        CP_ASYNC16(uAhi + doff, (const char*)(g_Xhi + aoff));
        CP_ASYNC16(uAlo + doff, (const char*)(g_Xlo + aoff));
    }
#pragma unroll
    for (int t = 0; t < 4; t++) {
        int o = tid + t * 256;            // 0..1023
        int row = o >> 2, seg = o & 3;
        uint32_t doff = row * 80 + seg * 16;
        size_t boff = (size_t)(j0 + row) * D + kc + seg * 8;
        CP_ASYNC16(uBhi + doff, (const char*)(g_Whi + boff));
        CP_ASYNC16(uBlo + doff, (const char*)(g_Wlo + boff));
    }
}

__global__ __launch_bounds__(256, 1) void gemm_wmma_kernel(int M) {
    extern __shared__ char smem[];
    int tid = threadIdx.x;
    int wid = tid >> 5;
    int lane = tid & 31;
    int warp_row = wid & 1;       // 0..1 (64 rows each)
    int warp_col = wid >> 1;      // 0..3 (64 cols each)
    int row0 = blockIdx.x * 128;
    int j0 = blockIdx.y * 256;    // 0 = self half, 256 = neigh half

    wmma::fragment<wmma::accumulator, 16, 16, 16, float> acc[4][4];
#pragma unroll
    for (int i = 0; i < 4; i++)
#pragma unroll
        for (int j = 0; j < 4; j++) wmma::fill_fragment(acc[i][j], 0.f);

    gemm_stage_load(smem, 0, row0, j0, 0, tid);
    CP_COMMIT();

#pragma unroll
    for (int c = 0; c < 8; c++) {
        int s = c & 1;
        if (c + 1 < 8) {
            gemm_stage_load(smem, (c + 1) & 1, row0, j0, (c + 1) * 32, tid);
            CP_COMMIT();
            CP_WAIT(1);
        } else {
            CP_WAIT(0);
        }
        __syncthreads();

        const __nv_bfloat16* AsHi = (const __nv_bfloat16*)(smem + s * STAGE_BYTES);
        const __nv_bfloat16* AsLo = AsHi + 128 * GLDM;
        const __nv_bfloat16* BsHi = AsLo + 128 * GLDM;
        const __nv_bfloat16* BsLo = BsHi + 256 * GLDM;
#pragma unroll
        for (int ks = 0; ks < 2; ks++) {
            wmma::fragment<wmma::matrix_a, 16, 16, 16, __nv_bfloat16, wmma::row_major> aHi[4], aLo[4];
#pragma unroll
            for (int i = 0; i < 4; i++) {
                const __nv_bfloat16* pa = AsHi + (warp_row * 64 + i * 16) * GLDM + ks * 16;
                wmma::load_matrix_sync(aHi[i], pa, GLDM);
                wmma::load_matrix_sync(aLo[i], pa + 128 * GLDM, GLDM);
            }
#pragma unroll
            for (int j = 0; j < 4; j++) {
                wmma::fragment<wmma::matrix_b, 16, 16, 16, __nv_bfloat16, wmma::col_major> bHi, bLo;
                const __nv_bfloat16* pb = BsHi + (warp_col * 64 + j * 16) * GLDM + ks * 16;
                wmma::load_matrix_sync(bHi, pb, GLDM);
                wmma::load_matrix_sync(bLo, pb + 256 * GLDM, GLDM);
#pragma unroll
                for (int i = 0; i < 4; i++) {
                    wmma::mma_sync(acc[i][j], aHi[i], bHi, acc[i][j]);
                    wmma::mma_sync(acc[i][j], aHi[i], bLo, acc[i][j]);
                    wmma::mma_sync(acc[i][j], aLo[i], bHi, acc[i][j]);
                }
            }
        }
        __syncthreads();
    }

    // ---- fused epilogue: tile -> smem, per-row normalize, write out ----
    float* ebuf = (float*)smem;
#pragma unroll
    for (int i = 0; i < 4; i++)
#pragma unroll
        for (int j = 0; j < 4; j++)
            wmma::store_matrix_sync(ebuf + (warp_row * 64 + i * 16) * 256 + warp_col * 64 + j * 16,
                                    acc[i][j], 256, wmma::mem_row_major);
    __syncthreads();

    bool neigh = (blockIdx.y != 0);
    for (int r = wid * 16; r < wid * 16 + 16; r++) {
        const float* er = ebuf + r * 256;
        float v[8];
        float ss = 0.f;
#pragma unroll
        for (int k = 0; k < 8; k++) {
            float t = er[k * 32 + lane];
            v[k] = t;
            ss += t * t;
        }
        ss = warp_sum(ss);
        float inv = 1.f / fmaxf(sqrtf(ss), 1e-8f);
        bool zr = (ss == 0.f);
        size_t grow = (size_t)(row0 + r);
        if (!neigh) {
            float* q = g_Cs + grow * D;
#pragma unroll
            for (int k = 0; k < 8; k++)
                q[k * 32 + lane] = zr ? 0.0625f : v[k] * inv;
        } else {
            __half* q = g_Nh + grow * D;
#pragma unroll
            for (int k = 0; k < 8; k++)
                q[k * 32 + lane] = __float2half(zr ? 0.0625f : v[k] * inv);
        }
    }
}

// ---------------- 6. aggregation + blend + final normalize (1 warp / node) ------
__global__ void agg_kernel(float* __restrict__ out, int N) {
    int w = (blockIdx.x * blockDim.x + threadIdx.x) >> 5;
    int lane = threadIdx.x & 31;
    if (w >= N) return;
    int beg = g_off[w], end = g_off[w + 1];
    float accx[4] = {0.f, 0.f, 0.f, 0.f};
    float accy[4] = {0.f, 0.f, 0.f, 0.f};
    float acch = 0.f;
    const __half2* nh = (const __half2*)g_Nh;
    for (int e = beg; e < end; e++) {
        int c = g_bucket[e];
        const __half2* p = nh + (size_t)c * (D / 2);
#pragma unroll
        for (int k = 0; k < 4; k++) {
            float2 f = __half22float2(p[k * 32 + lane]);
            accx[k] += f.x;
            accy[k] += f.y;
        }
        acch += g_habs[c];
    }
    float ss = 0.f;
#pragma unroll
    for (int k = 0; k < 4; k++) ss += accx[k] * accx[k] + accy[k] * accy[k];
    ss = warp_sum(ss);
    float p2x[4], p2y[4];
    if (ss == 0.f) {
#pragma unroll
        for (int k = 0; k < 4; k++) { p2x[k] = 0.0625f; p2y[k] = 0.0625f; }
    } else {
        float iv = 1.f / fmaxf(sqrtf(ss), 1e-8f);
#pragma unroll
        for (int k = 0; k < 4; k++) { p2x[k] = accx[k] * iv; p2y[k] = accy[k] * iv; }
    }
    float p2h = 1.f + acch;
    const float t = 0.5f / (1.0f - 0.5f + 1e-8f);  // == 1.0f in fp32, as reference
    const float2* srow2 = (const float2*)(g_Cs + (size_t)w * D);  // normalized self
    float avx[4], avy[4];
    float ss2 = 0.f;
#pragma unroll
    for (int k = 0; k < 4; k++) {
        float2 s = srow2[k * 32 + lane];
        float ax = s.x * t + p2x[k];
        float ay = s.y * t + p2y[k];
        avx[k] = ax; avy[k] = ay;
        ss2 += ax * ax + ay * ay;
    }
    ss2 = warp_sum(ss2);
    float* orow = out + (size_t)w * (D + 1);
    if (ss2 == 0.f) {
#pragma unroll
        for (int k = 0; k < 4; k++) {
            int j = 2 * (k * 32 + lane);
            orow[j] = 0.0625f;
            orow[j + 1] = 0.0625f;
        }
    } else {
        float iv = 1.f / fmaxf(sqrtf(ss2), 1e-8f);
#pragma unroll
        for (int k = 0; k < 4; k++) {
            int j = 2 * (k * 32 + lane);
            orow[j] = avx[k] * iv;
            orow[j + 1] = avy[k] * iv;
        }
    }
    if (lane == 0) {
        float p1h = g_habs[w];
        orow[D] = (p1h * t + p2h) / (t + 1.0f);
        g_deg[w] = 0;   // reset for the next call's count_kernel
    }
}

// ---------------- launch --------------------------------------------------------
extern "C" void kernel_launch(void* const* d_in, const int* in_sizes, int n_in,
                              void* d_out, int out_size) {
    const float* x  = (const float*)d_in[0];
    const float* Ws = (const float*)d_in[1];
    const float* Wn = (const float*)d_in[2];
    const int*   ei = (const int*)d_in[3];
    int N = in_sizes[0] / (D + 1);
    if (N > NMAX) N = NMAX;
    int E = in_sizes[3] / 2;
    if (E > EMAX) E = EMAX;
    float* out = (float*)d_out;

    cudaFuncSetAttribute(gemm_wmma_kernel, cudaFuncAttributeMaxDynamicSharedMemorySize,
                         GEMM_SMEM);

    // Side stream + fork/join events: created ONCE on the first (non-capturing)
    // call; never destroyed. Capture calls only record/wait events on them.
    static cudaStream_t s2 = nullptr;
    static cudaEvent_t evF = nullptr, evJ = nullptr;
    if (s2 == nullptr) {
        cudaStreamCreateWithFlags(&s2, cudaStreamNonBlocking);
        cudaEventCreateWithFlags(&evF, cudaEventDisableTiming);
        cudaEventCreateWithFlags(&evJ, cudaEventDisableTiming);
    }

    int warpBlocks = (N * 32 + 255) / 256;
    int wsplitBlocks = (NC * D + 255) / 256;
    int NB = (N + 255) / 256;
    int EB = (E + 255) / 256;

    // Fork: edge-bucketing chain runs concurrently with the compute chain.
    cudaEventRecord(evF, (cudaStream_t)0);
    cudaStreamWaitEvent(s2, evF, 0);
    count_kernel<<<EB, 256, 0, s2>>>(ei, E);
    scan1_kernel<<<NB, 256, 0, s2>>>(N);
    scan2_kernel<<<1, 160, 0, s2>>>(NB, N);
    scan3_kernel<<<NB, 256, 0, s2>>>(N);
    fill_kernel<<<EB, 256, 0, s2>>>(ei, E);
    cudaEventRecord(evJ, s2);

    // Compute chain on the default (captured) stream.
    prep_wsplit_kernel<<<warpBlocks + wsplitBlocks, 256>>>(x, Ws, Wn, N, warpBlocks);
    dim3 gg((N + 127) / 128, 2);
    gemm_wmma_kernel<<<gg, 256, GEMM_SMEM>>>(N);

    // Join, then aggregate.
    cudaStreamWaitEvent((cudaStream_t)0, evJ, 0);
    agg_kernel<<<warpBlocks, 256>>>(out, N);
}